// round 3
// baseline (speedup 1.0000x reference)
#include <cuda_runtime.h>
#include <math.h>

#define N 542
#define LD 544
#define PLANE (LD*LD)
#define NIMG 24
#define NB 8
#define NC 3
#define KS 31
#define HF 15
#define TWO_PI 6.283185307179586476925286766559

// ---------------- persistent device scratch (zero-init at load) ----------------
__device__ float d_Fr[PLANE], d_Fi[PLANE];              // DFT matrix (symmetric), zero-padded rows/cols 542..543
__device__ float d_xA[NIMG*PLANE], d_xB[NIMG*PLANE];    // ping-pong spatial images
__device__ float d_Pr[NIMG*PLANE], d_Pi[NIMG*PLANE];    // complex work buffers
__device__ float d_Qr[NIMG*PLANE], d_Qi[NIMG*PLANE];
__device__ float d_Dkr[NB*PLANE], d_Dki[NB*PLANE];      // OTF of blur kernel per batch
__device__ float d_Dg[NC*PLANE];                        // exp(lam)*sum_f |Dg|^2 per channel
__device__ float d_Gr[NB*KS*LD], d_Gi[NB*KS*LD];        // separable OTF intermediate
__device__ float d_va[NB*LD], d_vb[NB*LD];              // edgetaper 1D windows

// ---------------- build DFT matrix ----------------
__global__ void build_F_kernel() {
    int idx = blockIdx.x * blockDim.x + threadIdx.x;
    if (idx >= PLANE) return;
    int i = idx / LD, j = idx % LD;
    float vr = 0.f, vi = 0.f;
    if (i < N && j < N) {
        long long m = ((long long)i * (long long)j) % N;
        double a = -TWO_PI * (double)m / (double)N;
        double s, c; sincos(a, &s, &c);
        vr = (float)c; vi = (float)s;   // e^{-2pi i u h / N}
    }
    d_Fr[idx] = vr; d_Fi[idx] = vi;
}

// ---------------- edge-replicate pad into xA; zero pads of both buffers ----------------
__global__ void pad_kernel(const float* __restrict__ y) {
    int idx = blockIdx.x * blockDim.x + threadIdx.x;
    if (idx >= NIMG * PLANE) return;
    int img = idx / PLANE, rem = idx % PLANE;
    int h = rem / LD, w = rem % LD;
    if (h >= N || w >= N) { d_xA[idx] = 0.f; d_xB[idx] = 0.f; return; }
    int ih = h - HF; ih = ih < 0 ? 0 : (ih > 511 ? 511 : ih);
    int iw = w - HF; iw = iw < 0 ? 0 : (iw > 511 ? 511 : iw);
    d_xA[idx] = y[((size_t)img * 512 + ih) * 512 + iw];
}

// ---------------- edgetaper windows via exact autocorrelation ----------------
__global__ void alpha_kernel(const float* __restrict__ k) {
    __shared__ float sk[KS*KS];
    __shared__ float p0[KS], p1[KS], c0[KS], c1[KS];
    __shared__ float m0s, m1s;
    int b = blockIdx.x, t = threadIdx.x;
    for (int i = t; i < KS*KS; i += 32) sk[i] = k[b*KS*KS + i];
    __syncwarp();
    if (t < KS) {
        float s0 = 0.f, s1 = 0.f;
        for (int j = 0; j < KS; j++) { s0 += sk[t*KS + j]; s1 += sk[j*KS + t]; }
        p0[t] = s0; p1[t] = s1;
    }
    __syncwarp();
    if (t < KS) {
        float a0 = 0.f, a1 = 0.f;
        for (int s = 0; s + t < KS; s++) { a0 += p0[s]*p0[s+t]; a1 += p1[s]*p1[s+t]; }
        c0[t] = a0; c1[t] = a1;
    }
    __syncwarp();
    if (t == 0) {
        float m = c0[0]; for (int i = 1; i < KS; i++) m = fmaxf(m, c0[i]); m0s = m;
        m = c1[0]; for (int i = 1; i < KS; i++) m = fmaxf(m, c1[i]); m1s = m;
    }
    __syncwarp();
    // circular autocorr over length 541; index 541 duplicates index 0 (ref concatenation)
    for (int h = t; h < LD; h += 32) {
        float v0 = 0.f, v1 = 0.f;
        if (h < N) {
            float r0 = (h <= 30) ? c0[h] : ((h >= N-31) ? c0[(N-1) - h] : 0.f);
            float r1 = (h <= 30) ? c1[h] : ((h >= N-31) ? c1[(N-1) - h] : 0.f);
            v0 = 1.f - r0 / m0s;
            v1 = 1.f - r1 / m1s;
        }
        d_va[b*LD + h] = v0;
        d_vb[b*LD + h] = v1;
    }
}

// ---------------- OTF of blur kernel (separable direct DFT over 31x31 support) ----------------
__global__ void otf1_kernel(const float* __restrict__ k) {
    int idx = blockIdx.x * blockDim.x + threadIdx.x;
    if (idx >= NB * KS * LD) return;
    int v = idx % LD;
    int s = (idx / LD) % KS;
    int b = idx / (LD * KS);
    float aR = 0.f, aI = 0.f;
    if (v < N) {
        for (int t = 0; t < KS; t++) {
            int mt = (t < HF) ? t + (N - HF) : t - HF;
            float w = k[b*KS*KS + s*KS + t];
            aR = fmaf(w, d_Fr[v*LD + mt], aR);
            aI = fmaf(w, d_Fi[v*LD + mt], aI);
        }
    }
    d_Gr[idx] = aR; d_Gi[idx] = aI;
}

__global__ void otf2_kernel() {
    int v = blockIdx.x * blockDim.x + threadIdx.x;
    if (v >= N) return;
    int u = blockIdx.y, b = blockIdx.z;
    float aR = 0.f, aI = 0.f;
    #pragma unroll
    for (int s = 0; s < KS; s++) {
        int ms = (s < HF) ? s + (N - HF) : s - HF;
        float fr = d_Fr[u*LD + ms], fi = d_Fi[u*LD + ms];
        float gr = d_Gr[(b*KS + s)*LD + v], gi = d_Gi[(b*KS + s)*LD + v];
        aR += fr*gr - fi*gi;
        aI += fr*gi + fi*gr;
    }
    d_Dkr[b*PLANE + u*LD + v] = aR;
    d_Dki[b*PLANE + u*LD + v] = aI;
}

// ---------------- exp(lam)*sum_f |OTF(filter_f,c)|^2 (3x3 support) ----------------
__global__ void dgsum_kernel(const float* __restrict__ filt, const float* __restrict__ lamp) {
    int v = blockIdx.x * blockDim.x + threadIdx.x;
    if (v >= N) return;
    int u = blockIdx.y, c = blockIdx.z;
    const int mi[3] = {N-1, 0, 1};   // (s-1) mod N for s=0,1,2
    float fur[3], fui[3], fvr[3], fvi[3];
    #pragma unroll
    for (int s = 0; s < 3; s++) {
        fur[s] = d_Fr[u*LD + mi[s]]; fui[s] = d_Fi[u*LD + mi[s]];
        fvr[s] = d_Fr[v*LD + mi[s]]; fvi[s] = d_Fi[v*LD + mi[s]];
    }
    float sum = 0.f;
    for (int f = 0; f < 8; f++) {
        float aR = 0.f, aI = 0.f;
        #pragma unroll
        for (int s = 0; s < 3; s++)
            #pragma unroll
            for (int t = 0; t < 3; t++) {
                float w = filt[(f*NC + c)*9 + s*3 + t];
                float er = fur[s]*fvr[t] - fui[s]*fvi[t];
                float ei = fur[s]*fvi[t] + fui[s]*fvr[t];
                aR = fmaf(w, er, aR);
                aI = fmaf(w, ei, aI);
            }
        sum += aR*aR + aI*aI;
    }
    d_Dg[c*PLANE + u*LD + v] = expf(lamp[0]) * sum;
}

// ---------------- edgetaper iteration: x_out = a*x + (1-a)*(k circ-conv x) ----------------
// dir: 0 => read xA write xB ; 1 => read xB write xA
__global__ __launch_bounds__(256) void conv_kernel(const float* __restrict__ kptr, int dir) {
    __shared__ float sk[KS*KS];
    __shared__ float sp[94*94];
    int img = blockIdx.z, b = img / NC;
    int h0 = blockIdx.y * 64, w0 = blockIdx.x * 64;
    int tx = threadIdx.x, ty = threadIdx.y;
    int tid = ty * 16 + tx;
    const float* xin = dir ? d_xB : d_xA;
    float* xout = dir ? d_xA : d_xB;
    const float* x = xin + (size_t)img * PLANE;

    for (int i = tid; i < KS*KS; i += 256) sk[i] = kptr[b*KS*KS + i];
    for (int i = tid; i < 94*94; i += 256) {
        int r = i / 94, cc = i % 94;
        int gh = h0 + r - HF; if (gh < 0) gh += N; if (gh >= N) gh -= N;
        int gw = w0 + cc - HF; if (gw < 0) gw += N; if (gw >= N) gw -= N;
        sp[i] = x[gh*LD + gw];
    }
    __syncthreads();

    float acc[4][4] = {};
    #pragma unroll 1
    for (int s = 0; s < KS; s++) {
        int rb0 = (ty*4 + 0 + 30 - s)*94 + tx;
        int rb1 = rb0 + 94, rb2 = rb1 + 94, rb3 = rb2 + 94;
        const float* krow = &sk[s*KS];
        #pragma unroll
        for (int t = 0; t < KS; t++) {
            float kv = krow[t];
            int off = 30 - t;
            acc[0][0] = fmaf(kv, sp[rb0+off    ], acc[0][0]);
            acc[0][1] = fmaf(kv, sp[rb0+off+16 ], acc[0][1]);
            acc[0][2] = fmaf(kv, sp[rb0+off+32 ], acc[0][2]);
            acc[0][3] = fmaf(kv, sp[rb0+off+48 ], acc[0][3]);
            acc[1][0] = fmaf(kv, sp[rb1+off    ], acc[1][0]);
            acc[1][1] = fmaf(kv, sp[rb1+off+16 ], acc[1][1]);
            acc[1][2] = fmaf(kv, sp[rb1+off+32 ], acc[1][2]);
            acc[1][3] = fmaf(kv, sp[rb1+off+48 ], acc[1][3]);
            acc[2][0] = fmaf(kv, sp[rb2+off    ], acc[2][0]);
            acc[2][1] = fmaf(kv, sp[rb2+off+16 ], acc[2][1]);
            acc[2][2] = fmaf(kv, sp[rb2+off+32 ], acc[2][2]);
            acc[2][3] = fmaf(kv, sp[rb2+off+48 ], acc[2][3]);
            acc[3][0] = fmaf(kv, sp[rb3+off    ], acc[3][0]);
            acc[3][1] = fmaf(kv, sp[rb3+off+16 ], acc[3][1]);
            acc[3][2] = fmaf(kv, sp[rb3+off+32 ], acc[3][2]);
            acc[3][3] = fmaf(kv, sp[rb3+off+48 ], acc[3][3]);
        }
    }
    #pragma unroll
    for (int r = 0; r < 4; r++) {
        int h = h0 + ty*4 + r;
        if (h >= N) continue;
        float vah = d_va[b*LD + h];
        #pragma unroll
        for (int c = 0; c < 4; c++) {
            int w = w0 + tx + 16*c;
            if (w >= N) continue;
            float a = vah * d_vb[b*LD + w];
            float xc = sp[(ty*4 + r + HF)*94 + tx + 16*c + HF];
            xout[(size_t)img*PLANE + h*LD + w] = a*xc + (1.f - a)*acc[r][c];
        }
    }
}

// ====================== matmul-DFT GEMM stages (64x64x16 tiles, 4x4 micro) ======================

// Stage A: T = F @ x  (complex A = F shared, real B = xB per-img) -> P
__global__ __launch_bounds__(256) void g1_fwd_kernel() {
    __shared__ float Asr[16][68], Asi[16][68], Bs[16][64];
    int img = blockIdx.z;
    const float* x = d_xB + (size_t)img * PLANE;
    int m0 = blockIdx.y * 64, n0 = blockIdx.x * 64;
    int tx = threadIdx.x, ty = threadIdx.y, tid = ty*16 + tx;
    int lar = tid >> 2, lac = (tid & 3) << 2;
    int lbr = tid >> 4, lbc = (tid & 15) << 2;
    float cr[4][4] = {}, ci[4][4] = {};
    for (int kk = 0; kk < LD; kk += 16) {
        float4 ar4, ai4, b4;
        if (m0 + lar < LD) {
            ar4 = *(const float4*)(d_Fr + (m0+lar)*LD + kk + lac);
            ai4 = *(const float4*)(d_Fi + (m0+lar)*LD + kk + lac);
        } else { ar4 = make_float4(0,0,0,0); ai4 = ar4; }
        if (n0 + lbc < LD) b4 = *(const float4*)(x + (kk+lbr)*LD + n0 + lbc);
        else b4 = make_float4(0,0,0,0);
        Asr[lac+0][lar]=ar4.x; Asr[lac+1][lar]=ar4.y; Asr[lac+2][lar]=ar4.z; Asr[lac+3][lar]=ar4.w;
        Asi[lac+0][lar]=ai4.x; Asi[lac+1][lar]=ai4.y; Asi[lac+2][lar]=ai4.z; Asi[lac+3][lar]=ai4.w;
        *(float4*)&Bs[lbr][lbc] = b4;
        __syncthreads();
        #pragma unroll
        for (int kq = 0; kq < 16; kq++) {
            float4 Ar = *(float4*)&Asr[kq][ty*4];
            float4 Ai = *(float4*)&Asi[kq][ty*4];
            float4 Bv = *(float4*)&Bs[kq][tx*4];
            float arr[4] = {Ar.x,Ar.y,Ar.z,Ar.w};
            float aii[4] = {Ai.x,Ai.y,Ai.z,Ai.w};
            float bb[4]  = {Bv.x,Bv.y,Bv.z,Bv.w};
            #pragma unroll
            for (int i = 0; i < 4; i++)
                #pragma unroll
                for (int j = 0; j < 4; j++) {
                    cr[i][j] = fmaf(arr[i], bb[j], cr[i][j]);
                    ci[i][j] = fmaf(aii[i], bb[j], ci[i][j]);
                }
        }
        __syncthreads();
    }
    float* pr = d_Pr + (size_t)img * PLANE;
    float* pi = d_Pi + (size_t)img * PLANE;
    if (n0 + tx*4 < LD) {
        #pragma unroll
        for (int i = 0; i < 4; i++) {
            int m = m0 + ty*4 + i;
            if (m < LD) {
                *(float4*)(pr + m*LD + n0 + tx*4) = make_float4(cr[i][0],cr[i][1],cr[i][2],cr[i][3]);
                *(float4*)(pi + m*LD + n0 + tx*4) = make_float4(ci[i][0],ci[i][1],ci[i][2],ci[i][3]);
            }
        }
    }
}

// Stage B (WIENER=true):  Q = (P @ F) .* [conj(Dk)/(|Dk|^2+Dg)]
// Stage C (WIENER=false): P = Q @ conj(F)   (SB = -1)
template<int SB, bool WIENER>
__global__ __launch_bounds__(256) void g2_row_kernel() {
    __shared__ float Asr[16][68], Asi[16][68], Bsr[16][64], Bsi[16][64];
    int img = blockIdx.z;
    const float* ar = (WIENER ? d_Pr : d_Qr) + (size_t)img * PLANE;
    const float* ai = (WIENER ? d_Pi : d_Qi) + (size_t)img * PLANE;
    float* cro = (WIENER ? d_Qr : d_Pr) + (size_t)img * PLANE;
    float* cio = (WIENER ? d_Qi : d_Pi) + (size_t)img * PLANE;
    int m0 = blockIdx.y * 64, n0 = blockIdx.x * 64;
    int tx = threadIdx.x, ty = threadIdx.y, tid = ty*16 + tx;
    int lar = tid >> 2, lac = (tid & 3) << 2;
    int lbr = tid >> 4, lbc = (tid & 15) << 2;
    float cr[4][4] = {}, ci[4][4] = {};
    for (int kk = 0; kk < LD; kk += 16) {
        float4 ar4, ai4, br4, bi4;
        if (m0 + lar < LD) {
            ar4 = *(const float4*)(ar + (m0+lar)*LD + kk + lac);
            ai4 = *(const float4*)(ai + (m0+lar)*LD + kk + lac);
        } else { ar4 = make_float4(0,0,0,0); ai4 = ar4; }
        if (n0 + lbc < LD) {
            br4 = *(const float4*)(d_Fr + (kk+lbr)*LD + n0 + lbc);
            bi4 = *(const float4*)(d_Fi + (kk+lbr)*LD + n0 + lbc);
        } else { br4 = make_float4(0,0,0,0); bi4 = br4; }
        Asr[lac+0][lar]=ar4.x; Asr[lac+1][lar]=ar4.y; Asr[lac+2][lar]=ar4.z; Asr[lac+3][lar]=ar4.w;
        Asi[lac+0][lar]=ai4.x; Asi[lac+1][lar]=ai4.y; Asi[lac+2][lar]=ai4.z; Asi[lac+3][lar]=ai4.w;
        *(float4*)&Bsr[lbr][lbc] = br4;
        *(float4*)&Bsi[lbr][lbc] = bi4;
        __syncthreads();
        #pragma unroll
        for (int kq = 0; kq < 16; kq++) {
            float4 Ar = *(float4*)&Asr[kq][ty*4];
            float4 Ai = *(float4*)&Asi[kq][ty*4];
            float4 Br = *(float4*)&Bsr[kq][tx*4];
            float4 Bi = *(float4*)&Bsi[kq][tx*4];
            float arr[4] = {Ar.x,Ar.y,Ar.z,Ar.w};
            float aii[4] = {Ai.x,Ai.y,Ai.z,Ai.w};
            float brr[4] = {Br.x,Br.y,Br.z,Br.w};
            float bii[4] = {Bi.x,Bi.y,Bi.z,Bi.w};
            #pragma unroll
            for (int i = 0; i < 4; i++)
                #pragma unroll
                for (int j = 0; j < 4; j++) {
                    cr[i][j] = fmaf(arr[i], brr[j], cr[i][j]);
                    ci[i][j] = fmaf(aii[i], brr[j], ci[i][j]);
                    if (SB == 1) {
                        cr[i][j] = fmaf(-aii[i], bii[j], cr[i][j]);
                        ci[i][j] = fmaf( arr[i], bii[j], ci[i][j]);
                    } else {
                        cr[i][j] = fmaf( aii[i], bii[j], cr[i][j]);
                        ci[i][j] = fmaf(-arr[i], bii[j], ci[i][j]);
                    }
                }
        }
        __syncthreads();
    }
    int bq = img / NC, cq = img % NC;
    #pragma unroll
    for (int i = 0; i < 4; i++) {
        int m = m0 + ty*4 + i;
        if (m >= LD) continue;
        #pragma unroll
        for (int j = 0; j < 4; j++) {
            int n = n0 + tx*4 + j;
            if (n >= LD) continue;
            float sr = cr[i][j], si = ci[i][j];
            if (WIENER) {
                if (m < N && n < N) {
                    float dr = d_Dkr[bq*PLANE + m*LD + n];
                    float di = d_Dki[bq*PLANE + m*LD + n];
                    float dg = d_Dg[cq*PLANE + m*LD + n];
                    float om = 1.0f / (dr*dr + di*di + dg);
                    float wr = dr * om, wi = -di * om;
                    float tr = sr*wr - si*wi;
                    float ti = sr*wi + si*wr;
                    sr = tr; si = ti;
                } else { sr = 0.f; si = 0.f; }
            }
            cro[m*LD + n] = sr;
            cio[m*LD + n] = si;
        }
    }
}

// Stage D: out = (1/N^2) * Re[ conj(F) @ U ] = (Fr@Ur + Fi@Ui)/N^2  (F symmetric)
__global__ __launch_bounds__(256) void g3_out_kernel(float* __restrict__ out) {
    __shared__ float Asr[16][68], Asi[16][68], Bsr[16][64], Bsi[16][64];
    int img = blockIdx.z;
    const float* br = d_Pr + (size_t)img * PLANE;
    const float* bi = d_Pi + (size_t)img * PLANE;
    int m0 = blockIdx.y * 64, n0 = blockIdx.x * 64;
    int tx = threadIdx.x, ty = threadIdx.y, tid = ty*16 + tx;
    int lar = tid >> 2, lac = (tid & 3) << 2;
    int lbr = tid >> 4, lbc = (tid & 15) << 2;
    float acc[4][4] = {};
    for (int kk = 0; kk < LD; kk += 16) {
        float4 ar4, ai4, br4, bi4;
        if (m0 + lar < LD) {
            ar4 = *(const float4*)(d_Fr + (m0+lar)*LD + kk + lac);
            ai4 = *(const float4*)(d_Fi + (m0+lar)*LD + kk + lac);
        } else { ar4 = make_float4(0,0,0,0); ai4 = ar4; }
        if (n0 + lbc < LD) {
            br4 = *(const float4*)(br + (kk+lbr)*LD + n0 + lbc);
            bi4 = *(const float4*)(bi + (kk+lbr)*LD + n0 + lbc);
        } else { br4 = make_float4(0,0,0,0); bi4 = br4; }
        Asr[lac+0][lar]=ar4.x; Asr[lac+1][lar]=ar4.y; Asr[lac+2][lar]=ar4.z; Asr[lac+3][lar]=ar4.w;
        Asi[lac+0][lar]=ai4.x; Asi[lac+1][lar]=ai4.y; Asi[lac+2][lar]=ai4.z; Asi[lac+3][lar]=ai4.w;
        *(float4*)&Bsr[lbr][lbc] = br4;
        *(float4*)&Bsi[lbr][lbc] = bi4;
        __syncthreads();
        #pragma unroll
        for (int kq = 0; kq < 16; kq++) {
            float4 Ar = *(float4*)&Asr[kq][ty*4];
            float4 Ai = *(float4*)&Asi[kq][ty*4];
            float4 Br = *(float4*)&Bsr[kq][tx*4];
            float4 Bi = *(float4*)&Bsi[kq][tx*4];
            float arr[4] = {Ar.x,Ar.y,Ar.z,Ar.w};
            float aii[4] = {Ai.x,Ai.y,Ai.z,Ai.w};
            float brr[4] = {Br.x,Br.y,Br.z,Br.w};
            float bii[4] = {Bi.x,Bi.y,Bi.z,Bi.w};
            #pragma unroll
            for (int i = 0; i < 4; i++)
                #pragma unroll
                for (int j = 0; j < 4; j++) {
                    acc[i][j] = fmaf(arr[i], brr[j], acc[i][j]);
                    acc[i][j] = fmaf(aii[i], bii[j], acc[i][j]);
                }
        }
        __syncthreads();
    }
    const float scale = 1.0f / ((float)N * (float)N);
    #pragma unroll
    for (int i = 0; i < 4; i++) {
        int m = m0 + ty*4 + i;
        if (m >= N) continue;
        #pragma unroll
        for (int j = 0; j < 4; j++) {
            int n = n0 + tx*4 + j;
            if (n < N)
                out[((size_t)img * N + m) * N + n] = acc[i][j] * scale;
        }
    }
}

// ---------------- launcher ----------------
extern "C" void kernel_launch(void* const* d_in, const int* in_sizes, int n_in,
                              void* d_out, int out_size) {
    const float* y       = (const float*)d_in[0];   // [8,3,512,512]
    const float* k       = (const float*)d_in[1];   // [8,1,31,31]
    const float* lam     = (const float*)d_in[2];   // scalar
    const float* filters = (const float*)d_in[3];   // [8,3,3,3]
    float* out = (float*)d_out;

    build_F_kernel<<<(PLANE + 255)/256, 256>>>();
    pad_kernel<<<(NIMG*PLANE + 255)/256, 256>>>(y);
    alpha_kernel<<<NB, 32>>>(k);
    otf1_kernel<<<(NB*KS*LD + 255)/256, 256>>>(k);
    {
        dim3 g((LD + 127)/128, N, NB);
        otf2_kernel<<<g, 128>>>();
    }
    {
        dim3 g((LD + 127)/128, N, NC);
        dgsum_kernel<<<g, 128>>>(filters, lam);
    }
    dim3 cgrid((N + 63)/64, (N + 63)/64, NIMG), cblk(16, 16);
    conv_kernel<<<cgrid, cblk>>>(k, 0);   // xA -> xB
    conv_kernel<<<cgrid, cblk>>>(k, 1);   // xB -> xA
    conv_kernel<<<cgrid, cblk>>>(k, 0);   // xA -> xB  (final edgetapered image in xB)

    dim3 ggrid((LD + 63)/64 + ((LD % 64) ? 0 : 0), (LD + 63)/64, NIMG);
    // ceil(544/64)=9, but last tile partially out of range -> predicated; use 9x9
    dim3 ggrid2(9, 9, NIMG);
    g1_fwd_kernel<<<ggrid2, cblk>>>();                 // P = F @ x
    g2_row_kernel<1,  true ><<<ggrid2, cblk>>>();      // Q = (P @ F) .* Wiener
    g2_row_kernel<-1, false><<<ggrid2, cblk>>>();      // P = Q @ conj(F)
    g3_out_kernel<<<ggrid2, cblk>>>(out);              // out = Re[conj(F) @ P] / N^2
}

// round 5
// speedup vs baseline: 2.2503x; 2.2503x over previous
#include <cuda_runtime.h>
#include <math.h>

#define N 542
#define LD 544
#define PLANE (LD*LD)
#define NIMG 24
#define NB 8
#define NC 3
#define KS 31
#define HF 15
#define NHALF 272            // Hermitian: independent rows 0..271
#define KPAD 288             // stage-D K padded to 16 multiple
#define TWO_PI 6.283185307179586476925286766559

// ---------------- persistent device scratch (zero-init at load) ----------------
__device__ float d_Fr[PLANE], d_Fi[PLANE];              // DFT matrix (symmetric), zero-padded rows/cols 542..543
__device__ float d_xA[NIMG*PLANE], d_xB[NIMG*PLANE];    // ping-pong spatial images
__device__ float d_Pr[NIMG*PLANE], d_Pi[NIMG*PLANE];    // complex work buffers
__device__ float d_Qr[NIMG*PLANE], d_Qi[NIMG*PLANE];
__device__ float d_Dkr[NB*PLANE], d_Dki[NB*PLANE];      // OTF of blur kernel per batch
__device__ float d_Dg[NC*PLANE];                        // exp(lam)*sum_f |Dg|^2 per channel
__device__ float d_Gr[NB*KS*LD], d_Gi[NB*KS*LD];        // separable OTF intermediate
__device__ float d_va[NB*LD], d_vb[NB*LD];              // edgetaper 1D windows

// ---------------- build DFT matrix ----------------
__global__ void build_F_kernel() {
    int idx = blockIdx.x * blockDim.x + threadIdx.x;
    if (idx >= PLANE) return;
    int i = idx / LD, j = idx % LD;
    float vr = 0.f, vi = 0.f;
    if (i < N && j < N) {
        long long m = ((long long)i * (long long)j) % N;
        double a = -TWO_PI * (double)m / (double)N;
        double s, c; sincos(a, &s, &c);
        vr = (float)c; vi = (float)s;   // e^{-2pi i u h / N}
    }
    d_Fr[idx] = vr; d_Fi[idx] = vi;
}

// ---------------- edge-replicate pad into xA; zero pads of both buffers ----------------
__global__ void pad_kernel(const float* __restrict__ y) {
    int idx = blockIdx.x * blockDim.x + threadIdx.x;
    if (idx >= NIMG * PLANE) return;
    int img = idx / PLANE, rem = idx % PLANE;
    int h = rem / LD, w = rem % LD;
    if (h >= N || w >= N) { d_xA[idx] = 0.f; d_xB[idx] = 0.f; return; }
    int ih = h - HF; ih = ih < 0 ? 0 : (ih > 511 ? 511 : ih);
    int iw = w - HF; iw = iw < 0 ? 0 : (iw > 511 ? 511 : iw);
    d_xA[idx] = y[((size_t)img * 512 + ih) * 512 + iw];
}

// ---------------- edgetaper windows via exact autocorrelation ----------------
__global__ void alpha_kernel(const float* __restrict__ k) {
    __shared__ float sk[KS*KS];
    __shared__ float p0[KS], p1[KS], c0[KS], c1[KS];
    __shared__ float m0s, m1s;
    int b = blockIdx.x, t = threadIdx.x;
    for (int i = t; i < KS*KS; i += 32) sk[i] = k[b*KS*KS + i];
    __syncwarp();
    if (t < KS) {
        float s0 = 0.f, s1 = 0.f;
        for (int j = 0; j < KS; j++) { s0 += sk[t*KS + j]; s1 += sk[j*KS + t]; }
        p0[t] = s0; p1[t] = s1;
    }
    __syncwarp();
    if (t < KS) {
        float a0 = 0.f, a1 = 0.f;
        for (int s = 0; s + t < KS; s++) { a0 += p0[s]*p0[s+t]; a1 += p1[s]*p1[s+t]; }
        c0[t] = a0; c1[t] = a1;
    }
    __syncwarp();
    if (t == 0) {
        float m = c0[0]; for (int i = 1; i < KS; i++) m = fmaxf(m, c0[i]); m0s = m;
        m = c1[0]; for (int i = 1; i < KS; i++) m = fmaxf(m, c1[i]); m1s = m;
    }
    __syncwarp();
    for (int h = t; h < LD; h += 32) {
        float v0 = 0.f, v1 = 0.f;
        if (h < N) {
            float r0 = (h <= 30) ? c0[h] : ((h >= N-31) ? c0[(N-1) - h] : 0.f);
            float r1 = (h <= 30) ? c1[h] : ((h >= N-31) ? c1[(N-1) - h] : 0.f);
            v0 = 1.f - r0 / m0s;
            v1 = 1.f - r1 / m1s;
        }
        d_va[b*LD + h] = v0;
        d_vb[b*LD + h] = v1;
    }
}

// ---------------- OTF of blur kernel (separable direct DFT over 31x31 support) ----------------
__global__ void otf1_kernel(const float* __restrict__ k) {
    int idx = blockIdx.x * blockDim.x + threadIdx.x;
    if (idx >= NB * KS * LD) return;
    int v = idx % LD;
    int s = (idx / LD) % KS;
    int b = idx / (LD * KS);
    float aR = 0.f, aI = 0.f;
    if (v < N) {
        for (int t = 0; t < KS; t++) {
            int mt = (t < HF) ? t + (N - HF) : t - HF;
            float w = k[b*KS*KS + s*KS + t];
            aR = fmaf(w, d_Fr[v*LD + mt], aR);
            aI = fmaf(w, d_Fi[v*LD + mt], aI);
        }
    }
    d_Gr[idx] = aR; d_Gi[idx] = aI;
}

__global__ void otf2_kernel() {
    int v = blockIdx.x * blockDim.x + threadIdx.x;
    if (v >= N) return;
    int u = blockIdx.y, b = blockIdx.z;
    float aR = 0.f, aI = 0.f;
    #pragma unroll
    for (int s = 0; s < KS; s++) {
        int ms = (s < HF) ? s + (N - HF) : s - HF;
        float fr = d_Fr[u*LD + ms], fi = d_Fi[u*LD + ms];
        float gr = d_Gr[(b*KS + s)*LD + v], gi = d_Gi[(b*KS + s)*LD + v];
        aR += fr*gr - fi*gi;
        aI += fr*gi + fi*gr;
    }
    d_Dkr[b*PLANE + u*LD + v] = aR;
    d_Dki[b*PLANE + u*LD + v] = aI;
}

// ---------------- exp(lam)*sum_f |OTF(filter_f,c)|^2 (3x3 support) ----------------
__global__ void dgsum_kernel(const float* __restrict__ filt, const float* __restrict__ lamp) {
    int v = blockIdx.x * blockDim.x + threadIdx.x;
    if (v >= N) return;
    int u = blockIdx.y, c = blockIdx.z;
    const int mi[3] = {N-1, 0, 1};
    float fur[3], fui[3], fvr[3], fvi[3];
    #pragma unroll
    for (int s = 0; s < 3; s++) {
        fur[s] = d_Fr[u*LD + mi[s]]; fui[s] = d_Fi[u*LD + mi[s]];
        fvr[s] = d_Fr[v*LD + mi[s]]; fvi[s] = d_Fi[v*LD + mi[s]];
    }
    float sum = 0.f;
    for (int f = 0; f < 8; f++) {
        float aR = 0.f, aI = 0.f;
        #pragma unroll
        for (int s = 0; s < 3; s++)
            #pragma unroll
            for (int t = 0; t < 3; t++) {
                float w = filt[(f*NC + c)*9 + s*3 + t];
                float er = fur[s]*fvr[t] - fui[s]*fvi[t];
                float ei = fur[s]*fvi[t] + fui[s]*fvr[t];
                aR = fmaf(w, er, aR);
                aI = fmaf(w, ei, aI);
            }
        sum += aR*aR + aI*aI;
    }
    d_Dg[c*PLANE + u*LD + v] = expf(lamp[0]) * sum;
}

// ---------------- edgetaper iteration: x_out = a*x + (1-a)*(k circ-conv x) ----------------
// Vertical register reuse: each thread computes an 8-row x 1-col strip.
// Block (64,4) = 256 thr; tile 32 rows x 64 cols; smem halo tile 62x94.
// dir: 0 => read xA write xB ; 1 => read xB write xA
__global__ __launch_bounds__(256) void conv_kernel(const float* __restrict__ kptr, int dir) {
    __shared__ float skf[KS*KS];       // flipped kernel
    __shared__ float sp[62*94];
    int img = blockIdx.z, b = img / NC;
    int h0 = blockIdx.y * 32, w0 = blockIdx.x * 64;
    int tx = threadIdx.x, ty = threadIdx.y;
    int tid = ty * 64 + tx;
    const float* xin = dir ? d_xB : d_xA;
    float* xout = dir ? d_xA : d_xB;
    const float* x = xin + (size_t)img * PLANE;

    // flipped kernel: skf[ss*31+tt] = k[(30-ss)*31 + (30-tt)] = k[960 - idx]
    for (int i = tid; i < KS*KS; i += 256) skf[i] = kptr[b*KS*KS + 960 - i];
    // halo tile: origin (h0-15, w0-15), circular wrap
    for (int i = tid; i < 62*94; i += 256) {
        int r = i / 94, cc = i % 94;
        int gh = h0 + r - HF; if (gh < 0) gh += N; if (gh >= N) gh -= N;
        int gw = w0 + cc - HF; if (gw < 0) gw += N; if (gw >= N) gw -= N;
        sp[i] = x[gh*LD + gw];
    }
    __syncthreads();

    float acc[8] = {0.f,0.f,0.f,0.f,0.f,0.f,0.f,0.f};
    int rowbase = ty * 8;
    #pragma unroll 1
    for (int tt = 0; tt < KS; tt++) {
        float w[38];
        const float* col = &sp[rowbase*94 + tx + tt];
        #pragma unroll
        for (int q = 0; q < 38; q++) w[q] = col[q*94];
        #pragma unroll
        for (int ss = 0; ss < KS; ss++) {
            float kv = skf[ss*KS + tt];
            #pragma unroll
            for (int r = 0; r < 8; r++)
                acc[r] = fmaf(kv, w[r + ss], acc[r]);
        }
    }

    int w_g = w0 + tx;
    if (w_g < N) {
        float vbw = d_vb[b*LD + w_g];
        #pragma unroll
        for (int r = 0; r < 8; r++) {
            int h = h0 + rowbase + r;
            if (h >= N) continue;
            float a = d_va[b*LD + h] * vbw;
            float xc = sp[(rowbase + r + HF)*94 + tx + HF];
            xout[(size_t)img*PLANE + h*LD + w_g] = a*xc + (1.f - a)*acc[r];
        }
    }
}

// ====================== matmul-DFT GEMM stages (64x64x16 tiles, 4x4 micro) ======================
// Hermitian optimization: stages A,B,C compute only rows u = 0..271.

// Stage A: P = F @ x  (rows 0..271 only)
__global__ __launch_bounds__(256) void g1_fwd_kernel() {
    __shared__ float Asr[16][68], Asi[16][68], Bs[16][64];
    int img = blockIdx.z;
    const float* x = d_xB + (size_t)img * PLANE;
    int m0 = blockIdx.y * 64, n0 = blockIdx.x * 64;
    int tx = threadIdx.x, ty = threadIdx.y, tid = ty*16 + tx;
    int lar = tid >> 2, lac = (tid & 3) << 2;
    int lbr = tid >> 4, lbc = (tid & 15) << 2;
    float cr[4][4] = {}, ci[4][4] = {};
    for (int kk = 0; kk < LD; kk += 16) {
        float4 ar4 = *(const float4*)(d_Fr + (m0+lar)*LD + kk + lac);
        float4 ai4 = *(const float4*)(d_Fi + (m0+lar)*LD + kk + lac);
        float4 b4;
        if (n0 + lbc < LD) b4 = *(const float4*)(x + (kk+lbr)*LD + n0 + lbc);
        else b4 = make_float4(0,0,0,0);
        Asr[lac+0][lar]=ar4.x; Asr[lac+1][lar]=ar4.y; Asr[lac+2][lar]=ar4.z; Asr[lac+3][lar]=ar4.w;
        Asi[lac+0][lar]=ai4.x; Asi[lac+1][lar]=ai4.y; Asi[lac+2][lar]=ai4.z; Asi[lac+3][lar]=ai4.w;
        *(float4*)&Bs[lbr][lbc] = b4;
        __syncthreads();
        #pragma unroll
        for (int kq = 0; kq < 16; kq++) {
            float4 Ar = *(float4*)&Asr[kq][ty*4];
            float4 Ai = *(float4*)&Asi[kq][ty*4];
            float4 Bv = *(float4*)&Bs[kq][tx*4];
            float arr[4] = {Ar.x,Ar.y,Ar.z,Ar.w};
            float aii[4] = {Ai.x,Ai.y,Ai.z,Ai.w};
            float bb[4]  = {Bv.x,Bv.y,Bv.z,Bv.w};
            #pragma unroll
            for (int i = 0; i < 4; i++)
                #pragma unroll
                for (int j = 0; j < 4; j++) {
                    cr[i][j] = fmaf(arr[i], bb[j], cr[i][j]);
                    ci[i][j] = fmaf(aii[i], bb[j], ci[i][j]);
                }
        }
        __syncthreads();
    }
    float* pr = d_Pr + (size_t)img * PLANE;
    float* pi = d_Pi + (size_t)img * PLANE;
    if (n0 + tx*4 < LD) {
        #pragma unroll
        for (int i = 0; i < 4; i++) {
            int m = m0 + ty*4 + i;
            if (m < NHALF) {
                *(float4*)(pr + m*LD + n0 + tx*4) = make_float4(cr[i][0],cr[i][1],cr[i][2],cr[i][3]);
                *(float4*)(pi + m*LD + n0 + tx*4) = make_float4(ci[i][0],ci[i][1],ci[i][2],ci[i][3]);
            }
        }
    }
}

// Stage B (WIENER=true):  Q = [(P @ F) .* conj(Dk)/(|Dk|^2+Dg)] * rowweight   (rows 0..271)
// Stage C (WIENER=false): P = Q @ conj(F)   (SB = -1; rows 0..271; rows 272..287 zeroed)
template<int SB, bool WIENER>
__global__ __launch_bounds__(256) void g2_row_kernel() {
    __shared__ float Asr[16][68], Asi[16][68], Bsr[16][64], Bsi[16][64];
    int img = blockIdx.z;
    const float* ar = (WIENER ? d_Pr : d_Qr) + (size_t)img * PLANE;
    const float* ai = (WIENER ? d_Pi : d_Qi) + (size_t)img * PLANE;
    float* cro = (WIENER ? d_Qr : d_Pr) + (size_t)img * PLANE;
    float* cio = (WIENER ? d_Qi : d_Pi) + (size_t)img * PLANE;
    int m0 = blockIdx.y * 64, n0 = blockIdx.x * 64;
    int tx = threadIdx.x, ty = threadIdx.y, tid = ty*16 + tx;
    int lar = tid >> 2, lac = (tid & 3) << 2;
    int lbr = tid >> 4, lbc = (tid & 15) << 2;
    float cr[4][4] = {}, ci[4][4] = {};
    for (int kk = 0; kk < LD; kk += 16) {
        float4 ar4 = *(const float4*)(ar + (m0+lar)*LD + kk + lac);
        float4 ai4 = *(const float4*)(ai + (m0+lar)*LD + kk + lac);
        float4 br4, bi4;
        if (n0 + lbc < LD) {
            br4 = *(const float4*)(d_Fr + (kk+lbr)*LD + n0 + lbc);
            bi4 = *(const float4*)(d_Fi + (kk+lbr)*LD + n0 + lbc);
        } else { br4 = make_float4(0,0,0,0); bi4 = br4; }
        Asr[lac+0][lar]=ar4.x; Asr[lac+1][lar]=ar4.y; Asr[lac+2][lar]=ar4.z; Asr[lac+3][lar]=ar4.w;
        Asi[lac+0][lar]=ai4.x; Asi[lac+1][lar]=ai4.y; Asi[lac+2][lar]=ai4.z; Asi[lac+3][lar]=ai4.w;
        *(float4*)&Bsr[lbr][lbc] = br4;
        *(float4*)&Bsi[lbr][lbc] = bi4;
        __syncthreads();
        #pragma unroll
        for (int kq = 0; kq < 16; kq++) {
            float4 Ar = *(float4*)&Asr[kq][ty*4];
            float4 Ai = *(float4*)&Asi[kq][ty*4];
            float4 Br = *(float4*)&Bsr[kq][tx*4];
            float4 Bi = *(float4*)&Bsi[kq][tx*4];
            float arr[4] = {Ar.x,Ar.y,Ar.z,Ar.w};
            float aii[4] = {Ai.x,Ai.y,Ai.z,Ai.w};
            float brr[4] = {Br.x,Br.y,Br.z,Br.w};
            float bii[4] = {Bi.x,Bi.y,Bi.z,Bi.w};
            #pragma unroll
            for (int i = 0; i < 4; i++)
                #pragma unroll
                for (int j = 0; j < 4; j++) {
                    cr[i][j] = fmaf(arr[i], brr[j], cr[i][j]);
                    ci[i][j] = fmaf(aii[i], brr[j], ci[i][j]);
                    if (SB == 1) {
                        cr[i][j] = fmaf(-aii[i], bii[j], cr[i][j]);
                        ci[i][j] = fmaf( arr[i], bii[j], ci[i][j]);
                    } else {
                        cr[i][j] = fmaf( aii[i], bii[j], cr[i][j]);
                        ci[i][j] = fmaf(-arr[i], bii[j], ci[i][j]);
                    }
                }
        }
        __syncthreads();
    }
    int bq = img / NC, cq = img % NC;
    #pragma unroll
    for (int i = 0; i < 4; i++) {
        int m = m0 + ty*4 + i;
        if (WIENER) {
            if (m >= NHALF) continue;
            float wu = (m == 0 || m == NHALF-1) ? 1.0f : 2.0f;   // Hermitian row weight
            #pragma unroll
            for (int j = 0; j < 4; j++) {
                int n = n0 + tx*4 + j;
                if (n >= LD) continue;
                float sr = cr[i][j], si = ci[i][j];
                if (m < N && n < N) {
                    float dr = d_Dkr[bq*PLANE + m*LD + n];
                    float di = d_Dki[bq*PLANE + m*LD + n];
                    float dg = d_Dg[cq*PLANE + m*LD + n];
                    float om = wu / (dr*dr + di*di + dg);
                    float wr = dr * om, wi = -di * om;
                    float tr = sr*wr - si*wi;
                    float ti = sr*wi + si*wr;
                    sr = tr; si = ti;
                } else { sr = 0.f; si = 0.f; }
                cro[m*LD + n] = sr;
                cio[m*LD + n] = si;
            }
        } else {
            if (m >= KPAD) continue;
            bool zero = (m >= NHALF);
            #pragma unroll
            for (int j = 0; j < 4; j++) {
                int n = n0 + tx*4 + j;
                if (n >= LD) continue;
                cro[m*LD + n] = zero ? 0.f : cr[i][j];
                cio[m*LD + n] = zero ? 0.f : ci[i][j];
            }
        }
    }
}

// Stage D: out = (1/N^2) * [ Fr @ Zr + Fi @ Zi ]  over K = 272 weighted rows (padded to 288)
__global__ __launch_bounds__(256) void g3_out_kernel(float* __restrict__ out) {
    __shared__ float Asr[16][68], Asi[16][68], Bsr[16][64], Bsi[16][64];
    int img = blockIdx.z;
    const float* br = d_Pr + (size_t)img * PLANE;
    const float* bi = d_Pi + (size_t)img * PLANE;
    int m0 = blockIdx.y * 64, n0 = blockIdx.x * 64;
    int tx = threadIdx.x, ty = threadIdx.y, tid = ty*16 + tx;
    int lar = tid >> 2, lac = (tid & 3) << 2;
    int lbr = tid >> 4, lbc = (tid & 15) << 2;
    float acc[4][4] = {};
    for (int kk = 0; kk < KPAD; kk += 16) {
        float4 ar4, ai4, br4, bi4;
        if (m0 + lar < LD) {
            ar4 = *(const float4*)(d_Fr + (m0+lar)*LD + kk + lac);
            ai4 = *(const float4*)(d_Fi + (m0+lar)*LD + kk + lac);
        } else { ar4 = make_float4(0,0,0,0); ai4 = ar4; }
        if (n0 + lbc < LD) {
            br4 = *(const float4*)(br + (kk+lbr)*LD + n0 + lbc);
            bi4 = *(const float4*)(bi + (kk+lbr)*LD + n0 + lbc);
        } else { br4 = make_float4(0,0,0,0); bi4 = br4; }
        Asr[lac+0][lar]=ar4.x; Asr[lac+1][lar]=ar4.y; Asr[lac+2][lar]=ar4.z; Asr[lac+3][lar]=ar4.w;
        Asi[lac+0][lar]=ai4.x; Asi[lac+1][lar]=ai4.y; Asi[lac+2][lar]=ai4.z; Asi[lac+3][lar]=ai4.w;
        *(float4*)&Bsr[lbr][lbc] = br4;
        *(float4*)&Bsi[lbr][lbc] = bi4;
        __syncthreads();
        #pragma unroll
        for (int kq = 0; kq < 16; kq++) {
            float4 Ar = *(float4*)&Asr[kq][ty*4];
            float4 Ai = *(float4*)&Asi[kq][ty*4];
            float4 Br = *(float4*)&Bsr[kq][tx*4];
            float4 Bi = *(float4*)&Bsi[kq][tx*4];
            float arr[4] = {Ar.x,Ar.y,Ar.z,Ar.w};
            float aii[4] = {Ai.x,Ai.y,Ai.z,Ai.w};
            float brr[4] = {Br.x,Br.y,Br.z,Br.w};
            float bii[4] = {Bi.x,Bi.y,Bi.z,Bi.w};
            #pragma unroll
            for (int i = 0; i < 4; i++)
                #pragma unroll
                for (int j = 0; j < 4; j++) {
                    acc[i][j] = fmaf(arr[i], brr[j], acc[i][j]);
                    acc[i][j] = fmaf(aii[i], bii[j], acc[i][j]);
                }
        }
        __syncthreads();
    }
    const float scale = 1.0f / ((float)N * (float)N);
    #pragma unroll
    for (int i = 0; i < 4; i++) {
        int m = m0 + ty*4 + i;
        if (m >= N) continue;
        #pragma unroll
        for (int j = 0; j < 4; j++) {
            int n = n0 + tx*4 + j;
            if (n < N)
                out[((size_t)img * N + m) * N + n] = acc[i][j] * scale;
        }
    }
}

// ---------------- launcher ----------------
extern "C" void kernel_launch(void* const* d_in, const int* in_sizes, int n_in,
                              void* d_out, int out_size) {
    const float* y       = (const float*)d_in[0];   // [8,3,512,512]
    const float* k       = (const float*)d_in[1];   // [8,1,31,31]
    const float* lam     = (const float*)d_in[2];   // scalar
    const float* filters = (const float*)d_in[3];   // [8,3,3,3]
    float* out = (float*)d_out;

    build_F_kernel<<<(PLANE + 255)/256, 256>>>();
    pad_kernel<<<(NIMG*PLANE + 255)/256, 256>>>(y);
    alpha_kernel<<<NB, 32>>>(k);
    otf1_kernel<<<(NB*KS*LD + 255)/256, 256>>>(k);
    {
        dim3 g((LD + 127)/128, N, NB);
        otf2_kernel<<<g, 128>>>();
    }
    {
        dim3 g((LD + 127)/128, N, NC);
        dgsum_kernel<<<g, 128>>>(filters, lam);
    }
    dim3 cgrid((N + 63)/64, (N + 31)/32, NIMG), cblk2(64, 4);
    conv_kernel<<<cgrid, cblk2>>>(k, 0);   // xA -> xB
    conv_kernel<<<cgrid, cblk2>>>(k, 1);   // xB -> xA
    conv_kernel<<<cgrid, cblk2>>>(k, 0);   // xA -> xB  (final edgetapered image in xB)

    dim3 cblk(16, 16);
    dim3 gridD(9, 9, NIMG);
    g1_fwd_kernel<<<dim3(9,5,NIMG), cblk>>>();            // P = F @ x            (272 rows)
    g2_row_kernel<1,  true ><<<dim3(9,5,NIMG), cblk>>>(); // Q = (P@F).*W*wu      (272 rows)
    g2_row_kernel<-1, false><<<dim3(9,5,NIMG), cblk>>>(); // Z = Q @ conj(F)      (272 rows + zero pad)
    g3_out_kernel<<<gridD, cblk>>>(out);                  // out = (Fr@Zr+Fi@Zi)/N^2, K=288
}